// round 17
// baseline (speedup 1.0000x reference)
#include <cuda_runtime.h>
#include <cuda_bf16.h>
#include <math_constants.h>
#include <cstdint>

// Problem constants
#define NB   16
#define NC   1024
#define NT   16
#define NP   360          // H*W = 12*30
#define NK   120          // top-k
#define ROWS 482          // 1 + 120 + 1 + 360
#define TSTRIDE ((size_t)NT * NP)   // 5760 floats between consecutive c

// Grid: 512 f0 blocks (b, ct) then 16 sort blocks. All 528 co-resident:
// __launch_bounds__(256,4) caps regs at 64; smem 4 x 51.9KB <= 227KB/SM
// -> 4 blocks/SM guaranteed -> capacity 592 >= 528.
#define N_F0   512
#define GRID   (N_F0 + NB)

// dynamic smem layout (floats): 3 subtiles of [4][1057] + cls[32]
// subtile s holds p in [128s, 128s+128); component j at [s*4228 + j*1057 + c*33 + pq]
// maps x[c][p] with p = 128s + 4*pq + j   (conflict-free on all access patterns)
#define SUBF   4228
#define CLSOFF (3 * SUBF)
#define SMEM_BYTES ((3 * SUBF + 32) * 4)   // 50864 B

// Scratch (no device allocation allowed -> __device__ globals)
__device__ __align__(16) float g_spart[NB][32][NP];
__device__ int g_topk[NB][128];
__device__ int g_cnt[NB * 32];    // per-b f0-block counters (128B padded), init 0
__device__ int g_flag[NB * 32];   // per-b sort-done flag
__device__ int g_done[NB * 32];   // per-b f0-block completion (for flag reset)

__global__ void __launch_bounds__(256, 4) k_all(const float* __restrict__ x,
                                                const float* __restrict__ cls,
                                                float* __restrict__ out)
{
    extern __shared__ float sbuf[];
    const int bid = blockIdx.x;
    const int tid = threadIdx.x;

    if (bid < N_F0) {
        // ================= f0 block (b, ct): 32c x 360p ====================
        const int b  = bid >> 5;
        const int ct = bid & 31;
        float* cls_s = sbuf + CLSOFF;

        if (tid < 32)
            cls_s[tid] = cls[b * (NT * NC) + ct * 32 + tid];   // t=0 cls

        const float* x0 = x + ((size_t)(b * NC + ct * 32)) * TSTRIDE;  // t=0
        const float* x1 = x0 + NP;                                     // t=1

        // ---- load f0 tile: 2880 float4, fully coalesced over p ----
        #pragma unroll
        for (int i = 0; i < 12; ++i) {
            const int idx = tid + 256 * i;
            if (idx < 2880) {
                const int cl = idx / 90;
                const int q  = idx - cl * 90;       // p-quad 0..89
                const float4 v = *reinterpret_cast<const float4*>(
                    x0 + (size_t)cl * TSTRIDE + 4 * q);
                const int s = q >> 5, pq = q & 31;
                float* tp = sbuf + s * SUBF + cl * 33 + pq;
                tp[0]        = v.x;
                tp[1057]     = v.y;
                tp[2 * 1057] = v.z;
                tp[3 * 1057] = v.w;
            }
        }
        __syncthreads();

        // ---- partial scores: thread-per-p dot over 32 c (deterministic) ---
        for (int p = tid; p < NP; p += 256) {
            const int s = p >> 7, pl = p & 127, j = pl & 3, pq = pl >> 2;
            const float* base = sbuf + s * SUBF + j * 1057 + pq;
            float a = 0.f;
            #pragma unroll
            for (int c2 = 0; c2 < 32; ++c2)
                a = fmaf(cls_s[c2], base[c2 * 33], a);
            g_spart[b][ct][p] = a;
        }
        __syncthreads();
        if (tid == 0)
            asm volatile("red.release.gpu.global.add.s32 [%0], 1;"
                         :: "l"(&g_cnt[b * 32]) : "memory");

        // ---- prefetch f1 p[0..256) into regs (overlaps sort wait) ----
        const int c  = tid >> 3;          // 0..31
        const int q0 = tid & 7;           // quad phase
        float4 v[8];
        #pragma unroll
        for (int k = 0; k < 8; ++k)
            v[k] = *reinterpret_cast<const float4*>(
                x1 + (size_t)c * TSTRIDE + 4 * (q0 + 8 * k));

        // ---- wait for this b's sort ----
        if (tid == 0) {
            int f;
            do {
                __nanosleep(128);
                asm volatile("ld.acquire.gpu.global.s32 %0, [%1];"
                             : "=r"(f) : "l"(&g_flag[b * 32]) : "memory");
            } while (f == 0);
        }
        __syncthreads();   // acquire propagates; topk visible

        // ---- write 120 selected rows straight from smem (no re-read) ----
        const size_t obase = (size_t)b * ROWS * NC;
        for (int idx = tid; idx < NK * 8; idx += 256) {
            const int rank = idx >> 3, cq = idx & 7;
            const int p = g_topk[b][rank];
            const int s = p >> 7, pl = p & 127, j = pl & 3, pq = pl >> 2;
            const float* base = sbuf + s * SUBF + j * 1057 + pq;
            float4 w;
            w.x = base[(4 * cq + 0) * 33];
            w.y = base[(4 * cq + 1) * 33];
            w.z = base[(4 * cq + 2) * 33];
            w.w = base[(4 * cq + 3) * 33];
            *reinterpret_cast<float4*>(
                out + obase + (size_t)(1 + rank) * NC + ct * 32 + cq * 4) = w;
        }

        // flag/done reset for next graph replay (all 32 blocks passed spin)
        if (tid == 0) {
            const int old = atomicAdd(&g_done[b * 32], 1);
            if (old == 31) { g_done[b * 32] = 0; g_flag[b * 32] = 0; }
        }

        // ---- f1 tail p[256..360): 832 float4 into temps ----
        float4 t[4];
        #pragma unroll
        for (int k = 0; k < 4; ++k) {
            const int idx = tid + 256 * k;
            if (idx < 832) {
                const int cl = idx / 26;
                const int q  = idx - cl * 26;   // 0..25 -> p = 256 + 4q + j
                t[k] = *reinterpret_cast<const float4*>(
                    x1 + (size_t)cl * TSTRIDE + 256 + 4 * q);
            }
        }
        __syncthreads();   // all selected-row reads of f0 smem complete

        // ---- dump f1 regs (p 0..255) into subtiles 0,1 ----
        #pragma unroll
        for (int k = 0; k < 8; ++k) {
            const int q = q0 + 8 * k;        // p-quad 0..63
            const int s = q >> 5, pq = q & 31;
            float* tp = sbuf + s * SUBF + c * 33 + pq;
            tp[0]        = v[k].x;
            tp[1057]     = v[k].y;
            tp[2 * 1057] = v[k].z;
            tp[3 * 1057] = v[k].w;
        }
        // ---- dump f1 tail into subtile 2 ----
        #pragma unroll
        for (int k = 0; k < 4; ++k) {
            const int idx = tid + 256 * k;
            if (idx < 832) {
                const int cl = idx / 26;
                const int q  = idx - cl * 26;
                float* tp = sbuf + 2 * SUBF + cl * 33 + q;
                tp[0]        = t[k].x;
                tp[1057]     = t[k].y;
                tp[2 * 1057] = t[k].z;
                tp[3 * 1057] = t[k].w;
            }
        }
        __syncthreads();

        // ---- f1 out: rows 122..481 ----
        for (int idx = tid; idx < NP * 8; idx += 256) {
            const int p = idx >> 3, cq = idx & 7;
            const int s = p >> 7, pl = p & 127, j = pl & 3, pq = pl >> 2;
            const float* base = sbuf + s * SUBF + j * 1057 + pq;
            float4 w;
            w.x = base[(4 * cq + 0) * 33];
            w.y = base[(4 * cq + 1) * 33];
            w.z = base[(4 * cq + 2) * 33];
            w.w = base[(4 * cq + 3) * 33];
            *reinterpret_cast<float4*>(
                out + obase + (size_t)(122 + p) * NC + ct * 32 + cq * 4) = w;
        }
    }
    else {
        // ================= sort block (one per b) ==========================
        const int b = bid - N_F0;
        float* sv = sbuf;                                 // [512]
        int*   si = reinterpret_cast<int*>(sbuf + 512);   // [512]

        if (tid == 0) {
            int vcnt;
            do {
                __nanosleep(64);
                asm volatile("ld.acquire.gpu.global.s32 %0, [%1];"
                             : "=r"(vcnt) : "l"(&g_cnt[b * 32]) : "memory");
            } while (vcnt < 32);   // 32 f0 blocks per b
            g_cnt[b * 32] = 0;     // reset for next replay (no more increments)
        }
        __syncthreads();   // acquire propagates

        for (int e = tid; e < 512; e += 256) {
            float vsum = -CUDART_INF_F;
            if (e < NP) {
                float a0 = 0.f, a1 = 0.f, a2 = 0.f, a3 = 0.f;
                #pragma unroll
                for (int k = 0; k < 32; k += 4) {
                    a0 += g_spart[b][k + 0][e];
                    a1 += g_spart[b][k + 1][e];
                    a2 += g_spart[b][k + 2][e];
                    a3 += g_spart[b][k + 3][e];
                }
                vsum = (a0 + a1) + (a2 + a3);
            }
            sv[e] = vsum;
            si[e] = e;
        }
        __syncthreads();

        // bitonic sort 512 (desc score, asc idx tiebreak = lax.top_k)
        for (int k = 2; k <= 512; k <<= 1) {
            for (int j = k >> 1; j > 0; j >>= 1) {
                const int l = 2 * tid - (tid & (j - 1));   // l & j == 0
                const int m = l | j;
                const float a = sv[l], cc = sv[m];
                const int   ia = si[l], ic = si[m];
                const bool a_after = (a < cc) || (a == cc && ia > ic);
                const bool dir_desc = ((l & k) == 0);
                if (dir_desc ? a_after : !a_after) {
                    sv[l] = cc; sv[m] = a; si[l] = ic; si[m] = ia;
                }
                __syncthreads();
            }
        }

        if (tid < NK) g_topk[b][tid] = si[tid];

        // cls rows: row 0 = cls[b,0,:], row 121 = cls[b,1,:]
        const size_t obase = (size_t)b * ROWS * NC;
        const float4* c4 = reinterpret_cast<const float4*>(cls + (size_t)b * NT * NC);
        float4* o4 = reinterpret_cast<float4*>(out + obase);
        for (int cc = tid; cc < NC / 4; cc += 256) {
            o4[cc]                 = c4[cc];              // row 0   (t=0 cls)
            o4[121 * (NC/4) + cc]  = c4[(NC/4) + cc];     // row 121 (t=1 cls)
        }

        __syncthreads();   // topk + cls ordered before release
        if (tid == 0)
            asm volatile("red.release.gpu.global.add.s32 [%0], 1;"
                         :: "l"(&g_flag[b * 32]) : "memory");
    }
}

// ---------------------------------------------------------------------------
extern "C" void kernel_launch(void* const* d_in, const int* in_sizes, int n_in,
                              void* d_out, int out_size)
{
    const float* x   = (const float*)d_in[0];   // [16,1024,16,12,30]
    const float* cls = (const float*)d_in[1];   // [16,16,1024]
    float* out = (float*)d_out;                 // [16,482,1024]

    // opt-in dynamic smem (>48KB); host-side attribute, graph-safe
    cudaFuncSetAttribute(k_all, cudaFuncAttributeMaxDynamicSharedMemorySize,
                         SMEM_BYTES);
    k_all<<<GRID, 256, SMEM_BYTES>>>(x, cls, out);
}